// round 12
// baseline (speedup 1.0000x reference)
#include <cuda_runtime.h>
#include <cstdint>

// Causal GQA flash attention, TF32 mma.sync, fp32 I/O.
// Shapes hardcoded: B=4, S=2048, H=16, KH=4, D=128.
// BQ=128 (8 warps x 16 rows), BK=64. 1 CTA/SM.
// R12: partial Q hoist (cols 0-63 in regs, cols 64-127 in smem) to stay under
//      the 255-reg cap (R11 spilled at 255), + double-buffered K/V with one
//      barrier per tile.

namespace {
constexpr int B_ = 4, S_ = 2048, H_ = 16, KH_ = 4, D_ = 128;
constexpr int BQ = 128, BK = 64;
constexpr int NTQ = S_ / BQ;            // 16 q-tiles per (b,h)
constexpr int QSTR = 132;               // staging stride; bank (4g+tg) conflict-free
constexpr int KSTR = 132;
constexpr int VSTR = 136;               // bank (8tg+g) conflict-free
constexpr int PSTR = 68;                // bank (4g+tg) conflict-free
constexpr int QHSTR = 68;               // Q-half stride; 68 % 32 == 4 -> conflict-free
constexpr int NWARP = 8, THREADS = 256;
constexpr float SCALE_LOG2E = 0.08838834764831845f * 1.4426950408889634f;
// smem layout (floats): K0 V0 K1 V1 P Qhalf ; Q staged at offset 0 pre-loop.
constexpr int OFF_K0 = 0;
constexpr int OFF_V0 = OFF_K0 + BK * KSTR;            // 8448
constexpr int OFF_K1 = OFF_V0 + BK * VSTR;            // 17152
constexpr int OFF_V1 = OFF_K1 + BK * KSTR;            // 25600
constexpr int OFF_P  = OFF_V1 + BK * VSTR;            // 34304
constexpr int OFF_QH = OFF_P + NWARP * 16 * PSTR;     // 43008
constexpr int SMEM_FLOATS = OFF_QH + BQ * QHSTR;      // 51712
constexpr size_t SMEM_BYTES = SMEM_FLOATS * sizeof(float);  // 206,848 B
static_assert(BQ * QSTR <= OFF_QH, "Q staging must fit below Qhalf");
}  // namespace

__device__ __forceinline__ uint32_t f2tf(float x) {
  uint32_t r;
  asm("cvt.rna.tf32.f32 %0, %1;" : "=r"(r) : "f"(x));
  return r;
}

__device__ __forceinline__ void mma8(float c[4], uint32_t a0, uint32_t a1,
                                     uint32_t a2, uint32_t a3, uint32_t b0,
                                     uint32_t b1) {
  asm volatile(
      "mma.sync.aligned.m16n8k8.row.col.f32.tf32.tf32.f32 "
      "{%0,%1,%2,%3}, {%4,%5,%6,%7}, {%8,%9}, {%0,%1,%2,%3};"
      : "+f"(c[0]), "+f"(c[1]), "+f"(c[2]), "+f"(c[3])
      : "r"(a0), "r"(a1), "r"(a2), "r"(a3), "r"(b0), "r"(b1));
}

// Load one K/V tile (64 keys x 128 dims, fp32 -> tf32) into the given buffers.
__device__ __forceinline__ void load_kv(const float* __restrict__ kb,
                                        const float* __restrict__ vb,
                                        uint32_t* __restrict__ sKb,
                                        uint32_t* __restrict__ sVb, int tid) {
#pragma unroll
  for (int it = 0; it < (BK * (D_ / 4)) / THREADS; ++it) {
    int i = tid + it * THREADS;
    int row = i >> 5, c4 = (i & 31) << 2;
    float4 xk = *(const float4*)(kb + (size_t)row * KH_ * D_ + c4);
    uint4 tk = {f2tf(xk.x), f2tf(xk.y), f2tf(xk.z), f2tf(xk.w)};
    *(uint4*)(sKb + row * KSTR + c4) = tk;
    float4 xv = *(const float4*)(vb + (size_t)row * KH_ * D_ + c4);
    uint4 tv = {f2tf(xv.x), f2tf(xv.y), f2tf(xv.z), f2tf(xv.w)};
    *(uint4*)(sVb + row * VSTR + c4) = tv;
  }
}

__global__ __launch_bounds__(THREADS, 1)
void fa_tf32_kernel(const float* __restrict__ q, const float* __restrict__ k,
                    const float* __restrict__ v, float* __restrict__ out) {
  extern __shared__ float sm[];
  uint32_t* smu = (uint32_t*)sm;
  uint32_t* sKb[2] = {smu + OFF_K0, smu + OFF_K1};
  uint32_t* sVb[2] = {smu + OFF_V0, smu + OFF_V1};
  uint32_t* sP = smu + OFF_P;
  uint32_t* sQh = smu + OFF_QH;

  const int bx = blockIdx.x;
  const int iq = NTQ - 1 - bx / (B_ * H_);   // longest CTAs first
  const int bh = bx % (B_ * H_);
  const int b = bh / H_, h = bh % H_;
  const int kvh = h / (H_ / KH_);            // GQA: jnp.repeat -> h // 4
  const int q0 = iq * BQ;

  const int tid = threadIdx.x;
  const int w = tid >> 5, lane = tid & 31;
  const int g = lane >> 2, tg = lane & 3;
  const int r0 = w * 16;
  uint32_t* sPw = sP + w * 16 * PSTR;

  // ---- stage full Q tile (128x128) at smem offset 0, fp32 -> tf32 ----
  const float* qbase = q + ((size_t)(b * S_ + q0) * H_ + h) * D_;
  for (int i = tid; i < BQ * (D_ / 4); i += THREADS) {
    int row = i >> 5, c4 = (i & 31) << 2;
    float4 x = *(const float4*)(qbase + (size_t)row * H_ * D_ + c4);
    uint4 t = {f2tf(x.x), f2tf(x.y), f2tf(x.z), f2tf(x.w)};
    *(uint4*)(smu + row * QSTR + c4) = t;
  }
  __syncthreads();

  // ---- Q cols 0-63 -> registers (32 regs); cols 64-127 -> persistent smem ---
  uint32_t qf[8][4];
#pragma unroll
  for (int kk = 0; kk < 8; ++kk) {
    const int col = kk * 8 + tg;
    qf[kk][0] = smu[(r0 + g) * QSTR + col];
    qf[kk][1] = smu[(r0 + g + 8) * QSTR + col];
    qf[kk][2] = smu[(r0 + g) * QSTR + col + 4];
    qf[kk][3] = smu[(r0 + g + 8) * QSTR + col + 4];
  }
  for (int i = tid; i < BQ * 16; i += THREADS) {  // 16 float4 per row (64 cols)
    int row = i >> 4, c4 = (i & 15) << 2;
    uint4 t = *(uint4*)(smu + row * QSTR + 64 + c4);
    *(uint4*)(sQh + row * QHSTR + c4) = t;
  }
  __syncthreads();  // staging region free -> becomes K/V buffers

  float o[16][4];
#pragma unroll
  for (int i = 0; i < 16; i++) {
    o[i][0] = 0.f; o[i][1] = 0.f; o[i][2] = 0.f; o[i][3] = 0.f;
  }
  float mA = -1e30f, mB = -1e30f, lA = 0.f, lB = 0.f;

  const int jmax = 2 * iq + 1;
  const float* kh_base = k + ((size_t)b * S_ * KH_ + kvh) * D_;
  const float* vh_base = v + ((size_t)b * S_ * KH_ + kvh) * D_;

  // preload tile 0 into buffer 0
  load_kv(kh_base, vh_base, sKb[0], sVb[0], tid);

  for (int j = 0; j <= jmax; ++j) {
    __syncthreads();  // buf[j&1] stores visible; buf[1-(j&1)] free

    // issue next tile's load first: overlaps this tile's compute via warp skew
    if (j < jmax) {
      const size_t nb = (size_t)(j + 1) * BK * KH_ * D_;
      load_kv(kh_base + nb, vh_base + nb, sKb[(j + 1) & 1], sVb[(j + 1) & 1],
              tid);
    }

    const int kbase = j * BK;
    const uint32_t* sK = sKb[j & 1];
    const uint32_t* sV = sVb[j & 1];

    // warp-uniform skip of fully-masked tiles; every surviving row has >= 1
    // unmasked key (kbase % 64 == 0, (q0+r0) % 16 == 0)
    const bool active = (kbase <= q0 + r0);
    if (active) {
      // ---- S = Q K^T (16x64 per warp; 8 n-tiles, 16 k-steps over D) ----
      float sacc[8][4];
#pragma unroll
      for (int nt = 0; nt < 8; nt++) {
        sacc[nt][0] = 0.f; sacc[nt][1] = 0.f;
        sacc[nt][2] = 0.f; sacc[nt][3] = 0.f;
      }
      // k-steps 0-7: Q from registers
#pragma unroll
      for (int kk = 0; kk < 8; ++kk) {
        const int col = kk * 8 + tg;
#pragma unroll
        for (int nt = 0; nt < 8; ++nt) {
          uint32_t b0 = sK[(nt * 8 + g) * KSTR + col];
          uint32_t b1 = sK[(nt * 8 + g) * KSTR + col + 4];
          mma8(sacc[nt], qf[kk][0], qf[kk][1], qf[kk][2], qf[kk][3], b0, b1);
        }
      }
      // k-steps 8-15: Q from the persistent half-tile smem
#pragma unroll
      for (int kk = 0; kk < 8; ++kk) {
        const int colq = kk * 8 + tg;            // col within Qhalf (D 64..127)
        const int colk = 64 + kk * 8 + tg;       // col within K tile
        uint32_t a0 = sQh[(r0 + g) * QHSTR + colq];
        uint32_t a1 = sQh[(r0 + g + 8) * QHSTR + colq];
        uint32_t a2 = sQh[(r0 + g) * QHSTR + colq + 4];
        uint32_t a3 = sQh[(r0 + g + 8) * QHSTR + colq + 4];
#pragma unroll
        for (int nt = 0; nt < 8; ++nt) {
          uint32_t b0 = sK[(nt * 8 + g) * KSTR + colk];
          uint32_t b1 = sK[(nt * 8 + g) * KSTR + colk + 4];
          mma8(sacc[nt], a0, a1, a2, a3, b0, b1);
        }
      }

      // ---- scale + causal mask (log2 domain) ----
      const bool needMask = (kbase + BK - 1) > (q0 + r0);
#pragma unroll
      for (int nt = 0; nt < 8; ++nt) {
#pragma unroll
        for (int sl = 0; sl < 4; ++sl) {
          float t = sacc[nt][sl] * SCALE_LOG2E;
          if (needMask) {
            int qrow = q0 + r0 + g + ((sl & 2) ? 8 : 0);
            int kcol = kbase + nt * 8 + 2 * tg + (sl & 1);
            if (kcol > qrow) t = -1e30f;
          }
          sacc[nt][sl] = t;
        }
      }

      // ---- online softmax (rows g -> A, rows g+8 -> B) ----
      float txA = -1e30f, txB = -1e30f;
#pragma unroll
      for (int nt = 0; nt < 8; ++nt) {
        txA = fmaxf(txA, fmaxf(sacc[nt][0], sacc[nt][1]));
        txB = fmaxf(txB, fmaxf(sacc[nt][2], sacc[nt][3]));
      }
      txA = fmaxf(txA, __shfl_xor_sync(0xffffffffu, txA, 1));
      txA = fmaxf(txA, __shfl_xor_sync(0xffffffffu, txA, 2));
      txB = fmaxf(txB, __shfl_xor_sync(0xffffffffu, txB, 1));
      txB = fmaxf(txB, __shfl_xor_sync(0xffffffffu, txB, 2));
      const float mnA = fmaxf(mA, txA), mnB = fmaxf(mB, txB);
      const float alA = exp2f(mA - mnA), alB = exp2f(mB - mnB);
      mA = mnA; mB = mnB;
      float rsA = 0.f, rsB = 0.f;
#pragma unroll
      for (int nt = 0; nt < 8; ++nt) {
        float p0 = exp2f(sacc[nt][0] - mnA);
        float p1 = exp2f(sacc[nt][1] - mnA);
        float p2 = exp2f(sacc[nt][2] - mnB);
        float p3 = exp2f(sacc[nt][3] - mnB);
        rsA += p0 + p1; rsB += p2 + p3;
        sacc[nt][0] = p0; sacc[nt][1] = p1;
        sacc[nt][2] = p2; sacc[nt][3] = p3;
      }
      rsA += __shfl_xor_sync(0xffffffffu, rsA, 1);
      rsA += __shfl_xor_sync(0xffffffffu, rsA, 2);
      rsB += __shfl_xor_sync(0xffffffffu, rsB, 1);
      rsB += __shfl_xor_sync(0xffffffffu, rsB, 2);
      lA = lA * alA + rsA;
      lB = lB * alB + rsB;
#pragma unroll
      for (int nt = 0; nt < 16; ++nt) {
        o[nt][0] *= alA; o[nt][1] *= alA; o[nt][2] *= alB; o[nt][3] *= alB;
      }

      // ---- P -> per-warp smem (C-layout -> A-layout remap) ----
#pragma unroll
      for (int nt = 0; nt < 8; ++nt) {
        uint2 pA = {f2tf(sacc[nt][0]), f2tf(sacc[nt][1])};
        *(uint2*)(sPw + g * PSTR + nt * 8 + 2 * tg) = pA;
        uint2 pB = {f2tf(sacc[nt][2]), f2tf(sacc[nt][3])};
        *(uint2*)(sPw + (g + 8) * PSTR + nt * 8 + 2 * tg) = pB;
      }
      __syncwarp();

      // ---- O += P V (16 n-tiles over D=128, 8 k-steps over keys) ----
#pragma unroll
      for (int kk = 0; kk < 8; ++kk) {
        const int col = kk * 8 + tg;
        uint32_t a0 = sPw[g * PSTR + col];
        uint32_t a1 = sPw[(g + 8) * PSTR + col];
        uint32_t a2 = sPw[g * PSTR + col + 4];
        uint32_t a3 = sPw[(g + 8) * PSTR + col + 4];
#pragma unroll
        for (int nt = 0; nt < 16; ++nt) {
          uint32_t b0 = sV[(col)*VSTR + nt * 8 + g];
          uint32_t b1 = sV[(col + 4) * VSTR + nt * 8 + g];
          mma8(o[nt], a0, a1, a2, a3, b0, b1);
        }
      }
    }  // active
  }

  // ---- epilogue: O / l, store fp32 ----
  const float ilA = 1.0f / lA;
  const float ilB = 1.0f / lB;
  float* obase = out + ((size_t)(b * S_ + q0 + r0) * H_ + h) * D_;
#pragma unroll
  for (int nt = 0; nt < 16; ++nt) {
    int c = nt * 8 + 2 * tg;
    float2 vA = {o[nt][0] * ilA, o[nt][1] * ilA};
    *(float2*)(obase + (size_t)g * H_ * D_ + c) = vA;
    float2 vB = {o[nt][2] * ilB, o[nt][3] * ilB};
    *(float2*)(obase + (size_t)(g + 8) * H_ * D_ + c) = vB;
  }
}

extern "C" void kernel_launch(void* const* d_in, const int* in_sizes, int n_in,
                              void* d_out, int out_size) {
  const float* q = (const float*)d_in[0];
  const float* k = (const float*)d_in[1];
  const float* v = (const float*)d_in[2];
  // d_in[3] = cu_seqlens: equal-length (arange(B+1)*S), structure hardcoded.
  float* out = (float*)d_out;

  cudaFuncSetAttribute(fa_tf32_kernel,
                       cudaFuncAttributeMaxDynamicSharedMemorySize,
                       (int)SMEM_BYTES);
  dim3 grid(B_ * H_ * NTQ);  // 1024 CTAs, longest (iq=15) first
  fa_tf32_kernel<<<grid, THREADS, SMEM_BYTES>>>(q, k, v, out);
}

// round 15
// speedup vs baseline: 1.0825x; 1.0825x over previous
#include <cuda_runtime.h>
#include <cstdint>

// Causal GQA flash attention, TF32 mma.sync, fp32 I/O.
// Shapes hardcoded: B=4, S=2048, H=16, KH=4, D=128.
// BQ=128 (8 warps x 16 rows), BK=64. 1 CTA/SM.
// R14: same as R13 (cp.async double-buffered K/V, raw fp32 -> HW tf32
//      truncation; Q cols 0-63 in regs, 64-127 in smem) with the issue_kv
//      chunk-index bug fixed: a 128-float row is 32 x 16B chunks, not 8
//      (R13 decoded row = i>>3 -> rows 0..255 against a 64-row tile -> OOB).

namespace {
constexpr int B_ = 4, S_ = 2048, H_ = 16, KH_ = 4, D_ = 128;
constexpr int BQ = 128, BK = 64;
constexpr int NTQ = S_ / BQ;            // 16 q-tiles per (b,h)
constexpr int QSTR = 132;               // staging stride; bank (4g+tg) conflict-free
constexpr int KSTR = 132;
constexpr int VSTR = 136;               // bank (8tg+g) conflict-free
constexpr int PSTR = 68;                // bank (4g+tg) conflict-free
constexpr int QHSTR = 68;               // Q-half stride; 68 % 32 == 4 conflict-free
constexpr int NWARP = 8, THREADS = 256;
constexpr float SCALE_LOG2E = 0.08838834764831845f * 1.4426950408889634f;
// smem layout (floats): K0 V0 K1 V1 P Qhalf ; Q staged at offset 0 pre-loop.
constexpr int OFF_K0 = 0;
constexpr int OFF_V0 = OFF_K0 + BK * KSTR;            // 8448
constexpr int OFF_K1 = OFF_V0 + BK * VSTR;            // 17152
constexpr int OFF_V1 = OFF_K1 + BK * KSTR;            // 25600
constexpr int OFF_P  = OFF_V1 + BK * VSTR;            // 34304
constexpr int OFF_QH = OFF_P + NWARP * 16 * PSTR;     // 43008
constexpr int SMEM_FLOATS = OFF_QH + BQ * QHSTR;      // 51712
constexpr size_t SMEM_BYTES = SMEM_FLOATS * sizeof(float);  // 206,848 B
static_assert(BQ * QSTR <= OFF_QH, "Q staging must fit below Qhalf");
}  // namespace

__device__ __forceinline__ uint32_t f2tf(float x) {
  uint32_t r;
  asm("cvt.rna.tf32.f32 %0, %1;" : "=r"(r) : "f"(x));
  return r;
}

__device__ __forceinline__ void mma8(float c[4], uint32_t a0, uint32_t a1,
                                     uint32_t a2, uint32_t a3, uint32_t b0,
                                     uint32_t b1) {
  asm volatile(
      "mma.sync.aligned.m16n8k8.row.col.f32.tf32.tf32.f32 "
      "{%0,%1,%2,%3}, {%4,%5,%6,%7}, {%8,%9}, {%0,%1,%2,%3};"
      : "+f"(c[0]), "+f"(c[1]), "+f"(c[2]), "+f"(c[3])
      : "r"(a0), "r"(a1), "r"(a2), "r"(a3), "r"(b0), "r"(b1));
}

__device__ __forceinline__ void cpa16(uint32_t smem_addr, const void* gptr) {
  asm volatile("cp.async.cg.shared.global [%0], [%1], 16;" ::"r"(smem_addr),
               "l"(gptr));
}

// Issue cp.async for one K/V tile (64 rows x 128 fp32 each). No registers held.
// 64 rows x 32 chunks(16B) = 2048 chunks per tensor; 8 per thread per tensor.
__device__ __forceinline__ void issue_kv(const float* __restrict__ kb,
                                         const float* __restrict__ vb,
                                         uint32_t sKa, uint32_t sVa, int tid) {
#pragma unroll
  for (int it = 0; it < 8; ++it) {
    int i = tid + it * THREADS;
    int row = i >> 5;            // 0..63   (R13 bug: was i >> 3 -> 0..255 OOB)
    int c4 = (i & 31) << 2;      // 0..124 floats, 16B-aligned
    cpa16(sKa + (row * KSTR + c4) * 4, kb + (size_t)row * KH_ * D_ + c4);
    cpa16(sVa + (row * VSTR + c4) * 4, vb + (size_t)row * KH_ * D_ + c4);
  }
  asm volatile("cp.async.commit_group;");
}

__global__ __launch_bounds__(THREADS, 1)
void fa_tf32_kernel(const float* __restrict__ q, const float* __restrict__ k,
                    const float* __restrict__ v, float* __restrict__ out) {
  extern __shared__ float sm[];
  uint32_t* smu = (uint32_t*)sm;
  uint32_t* sKb[2] = {smu + OFF_K0, smu + OFF_K1};
  uint32_t* sVb[2] = {smu + OFF_V0, smu + OFF_V1};
  uint32_t* sP = smu + OFF_P;
  uint32_t* sQh = smu + OFF_QH;
  const uint32_t smem_base = (uint32_t)__cvta_generic_to_shared(sm);

  const int bx = blockIdx.x;
  const int iq = NTQ - 1 - bx / (B_ * H_);   // longest CTAs first
  const int bh = bx % (B_ * H_);
  const int b = bh / H_, h = bh % H_;
  const int kvh = h / (H_ / KH_);            // GQA: jnp.repeat -> h // 4
  const int q0 = iq * BQ;

  const int tid = threadIdx.x;
  const int w = tid >> 5, lane = tid & 31;
  const int g = lane >> 2, tg = lane & 3;
  const int r0 = w * 16;
  uint32_t* sPw = sP + w * 16 * PSTR;

  // ---- stage full Q tile (128x128) at smem offset 0, fp32 -> tf32 RNA ----
  const float* qbase = q + ((size_t)(b * S_ + q0) * H_ + h) * D_;
  for (int i = tid; i < BQ * (D_ / 4); i += THREADS) {
    int row = i >> 5, c4 = (i & 31) << 2;
    float4 x = *(const float4*)(qbase + (size_t)row * H_ * D_ + c4);
    uint4 t = {f2tf(x.x), f2tf(x.y), f2tf(x.z), f2tf(x.w)};
    *(uint4*)(smu + row * QSTR + c4) = t;
  }
  __syncthreads();

  // ---- Q cols 0-63 -> registers (32 regs); cols 64-127 -> persistent smem ---
  uint32_t qf[8][4];
#pragma unroll
  for (int kk = 0; kk < 8; ++kk) {
    const int col = kk * 8 + tg;
    qf[kk][0] = smu[(r0 + g) * QSTR + col];
    qf[kk][1] = smu[(r0 + g + 8) * QSTR + col];
    qf[kk][2] = smu[(r0 + g) * QSTR + col + 4];
    qf[kk][3] = smu[(r0 + g + 8) * QSTR + col + 4];
  }
  for (int i = tid; i < BQ * 16; i += THREADS) {  // 16 float4 per row (64 cols)
    int row = i >> 4, c4 = (i & 15) << 2;
    uint4 t = *(uint4*)(smu + row * QSTR + 64 + c4);
    *(uint4*)(sQh + row * QHSTR + c4) = t;
  }
  __syncthreads();  // staging region free -> becomes K/V cp.async buffers

  float o[16][4];
#pragma unroll
  for (int i = 0; i < 16; i++) {
    o[i][0] = 0.f; o[i][1] = 0.f; o[i][2] = 0.f; o[i][3] = 0.f;
  }
  float mA = -1e30f, mB = -1e30f, lA = 0.f, lB = 0.f;

  const int jmax = 2 * iq + 1;
  const float* kh_base = k + ((size_t)b * S_ * KH_ + kvh) * D_;
  const float* vh_base = v + ((size_t)b * S_ * KH_ + kvh) * D_;

  const uint32_t aK[2] = {smem_base + OFF_K0 * 4, smem_base + OFF_K1 * 4};
  const uint32_t aV[2] = {smem_base + OFF_V0 * 4, smem_base + OFF_V1 * 4};

  // preload tile 0 into buffer 0 (group pending)
  issue_kv(kh_base, vh_base, aK[0], aV[0], tid);

  for (int j = 0; j <= jmax; ++j) {
    // issue tile j+1 into the other buffer, then drain tile j's group
    if (j < jmax) {
      const size_t nb = (size_t)(j + 1) * BK * KH_ * D_;
      issue_kv(kh_base + nb, vh_base + nb, aK[(j + 1) & 1], aV[(j + 1) & 1],
               tid);
      asm volatile("cp.async.wait_group 1;");
    } else {
      asm volatile("cp.async.wait_group 0;");
    }
    __syncthreads();  // tile j visible to all warps

    const int kbase = j * BK;
    const uint32_t* sK = sKb[j & 1];
    const uint32_t* sV = sVb[j & 1];

    // warp-uniform skip of fully-masked tiles; every surviving row has >= 1
    // unmasked key (kbase % 64 == 0, (q0+r0) % 16 == 0)
    const bool active = (kbase <= q0 + r0);
    if (active) {
      // ---- S = Q K^T (16x64 per warp; 8 n-tiles, 16 k-steps over D) ----
      // K holds raw fp32 bits; mma.tf32 truncates (RZ) in hardware.
      float sacc[8][4];
#pragma unroll
      for (int nt = 0; nt < 8; nt++) {
        sacc[nt][0] = 0.f; sacc[nt][1] = 0.f;
        sacc[nt][2] = 0.f; sacc[nt][3] = 0.f;
      }
#pragma unroll
      for (int kk = 0; kk < 8; ++kk) {  // Q cols 0-63 from registers
        const int col = kk * 8 + tg;
#pragma unroll
        for (int nt = 0; nt < 8; ++nt) {
          uint32_t b0 = sK[(nt * 8 + g) * KSTR + col];
          uint32_t b1 = sK[(nt * 8 + g) * KSTR + col + 4];
          mma8(sacc[nt], qf[kk][0], qf[kk][1], qf[kk][2], qf[kk][3], b0, b1);
        }
      }
#pragma unroll
      for (int kk = 0; kk < 8; ++kk) {  // Q cols 64-127 from smem
        const int colq = kk * 8 + tg;
        const int colk = 64 + kk * 8 + tg;
        uint32_t a0 = sQh[(r0 + g) * QHSTR + colq];
        uint32_t a1 = sQh[(r0 + g + 8) * QHSTR + colq];
        uint32_t a2 = sQh[(r0 + g) * QHSTR + colq + 4];
        uint32_t a3 = sQh[(r0 + g + 8) * QHSTR + colq + 4];
#pragma unroll
        for (int nt = 0; nt < 8; ++nt) {
          uint32_t b0 = sK[(nt * 8 + g) * KSTR + colk];
          uint32_t b1 = sK[(nt * 8 + g) * KSTR + colk + 4];
          mma8(sacc[nt], a0, a1, a2, a3, b0, b1);
        }
      }

      // ---- scale + causal mask (log2 domain) ----
      const bool needMask = (kbase + BK - 1) > (q0 + r0);
#pragma unroll
      for (int nt = 0; nt < 8; ++nt) {
#pragma unroll
        for (int sl = 0; sl < 4; ++sl) {
          float t = sacc[nt][sl] * SCALE_LOG2E;
          if (needMask) {
            int qrow = q0 + r0 + g + ((sl & 2) ? 8 : 0);
            int kcol = kbase + nt * 8 + 2 * tg + (sl & 1);
            if (kcol > qrow) t = -1e30f;
          }
          sacc[nt][sl] = t;
        }
      }

      // ---- online softmax (rows g -> A, rows g+8 -> B) ----
      float txA = -1e30f, txB = -1e30f;
#pragma unroll
      for (int nt = 0; nt < 8; ++nt) {
        txA = fmaxf(txA, fmaxf(sacc[nt][0], sacc[nt][1]));
        txB = fmaxf(txB, fmaxf(sacc[nt][2], sacc[nt][3]));
      }
      txA = fmaxf(txA, __shfl_xor_sync(0xffffffffu, txA, 1));
      txA = fmaxf(txA, __shfl_xor_sync(0xffffffffu, txA, 2));
      txB = fmaxf(txB, __shfl_xor_sync(0xffffffffu, txB, 1));
      txB = fmaxf(txB, __shfl_xor_sync(0xffffffffu, txB, 2));
      const float mnA = fmaxf(mA, txA), mnB = fmaxf(mB, txB);
      const float alA = exp2f(mA - mnA), alB = exp2f(mB - mnB);
      mA = mnA; mB = mnB;
      float rsA = 0.f, rsB = 0.f;
#pragma unroll
      for (int nt = 0; nt < 8; ++nt) {
        float p0 = exp2f(sacc[nt][0] - mnA);
        float p1 = exp2f(sacc[nt][1] - mnA);
        float p2 = exp2f(sacc[nt][2] - mnB);
        float p3 = exp2f(sacc[nt][3] - mnB);
        rsA += p0 + p1; rsB += p2 + p3;
        sacc[nt][0] = p0; sacc[nt][1] = p1;
        sacc[nt][2] = p2; sacc[nt][3] = p3;
      }
      rsA += __shfl_xor_sync(0xffffffffu, rsA, 1);
      rsA += __shfl_xor_sync(0xffffffffu, rsA, 2);
      rsB += __shfl_xor_sync(0xffffffffu, rsB, 1);
      rsB += __shfl_xor_sync(0xffffffffu, rsB, 2);
      lA = lA * alA + rsA;
      lB = lB * alB + rsB;
#pragma unroll
      for (int nt = 0; nt < 16; ++nt) {
        o[nt][0] *= alA; o[nt][1] *= alA; o[nt][2] *= alB; o[nt][3] *= alB;
      }

      // ---- P -> per-warp smem (C-layout -> A-layout remap), RNA cvt ----
#pragma unroll
      for (int nt = 0; nt < 8; ++nt) {
        uint2 pA = {f2tf(sacc[nt][0]), f2tf(sacc[nt][1])};
        *(uint2*)(sPw + g * PSTR + nt * 8 + 2 * tg) = pA;
        uint2 pB = {f2tf(sacc[nt][2]), f2tf(sacc[nt][3])};
        *(uint2*)(sPw + (g + 8) * PSTR + nt * 8 + 2 * tg) = pB;
      }
      __syncwarp();

      // ---- O += P V (16 n-tiles over D=128, 8 k-steps over keys) ----
      // V raw fp32 bits; mma.tf32 truncates in hardware.
#pragma unroll
      for (int kk = 0; kk < 8; ++kk) {
        const int col = kk * 8 + tg;
        uint32_t a0 = sPw[g * PSTR + col];
        uint32_t a1 = sPw[(g + 8) * PSTR + col];
        uint32_t a2 = sPw[g * PSTR + col + 4];
        uint32_t a3 = sPw[(g + 8) * PSTR + col + 4];
#pragma unroll
        for (int nt = 0; nt < 16; ++nt) {
          uint32_t b0 = sV[(col)*VSTR + nt * 8 + g];
          uint32_t b1 = sV[(col + 4) * VSTR + nt * 8 + g];
          mma8(o[nt], a0, a1, a2, a3, b0, b1);
        }
      }
    }  // active
    __syncthreads();  // compute(j) done before iter j+1 issues tile j+2 here
  }

  // ---- epilogue: O / l, store fp32 ----
  const float ilA = 1.0f / lA;
  const float ilB = 1.0f / lB;
  float* obase = out + ((size_t)(b * S_ + q0 + r0) * H_ + h) * D_;
#pragma unroll
  for (int nt = 0; nt < 16; ++nt) {
    int c = nt * 8 + 2 * tg;
    float2 vA = {o[nt][0] * ilA, o[nt][1] * ilA};
    *(float2*)(obase + (size_t)g * H_ * D_ + c) = vA;
    float2 vB = {o[nt][2] * ilB, o[nt][3] * ilB};
    *(float2*)(obase + (size_t)(g + 8) * H_ * D_ + c) = vB;
  }
}

extern "C" void kernel_launch(void* const* d_in, const int* in_sizes, int n_in,
                              void* d_out, int out_size) {
  const float* q = (const float*)d_in[0];
  const float* k = (const float*)d_in[1];
  const float* v = (const float*)d_in[2];
  // d_in[3] = cu_seqlens: equal-length (arange(B+1)*S), structure hardcoded.
  float* out = (float*)d_out;

  cudaFuncSetAttribute(fa_tf32_kernel,
                       cudaFuncAttributeMaxDynamicSharedMemorySize,
                       (int)SMEM_BYTES);
  dim3 grid(B_ * H_ * NTQ);  // 1024 CTAs, longest (iq=15) first
  fa_tf32_kernel<<<grid, THREADS, SMEM_BYTES>>>(q, k, v, out);
}

// round 16
// speedup vs baseline: 1.2316x; 1.1377x over previous
#include <cuda_runtime.h>
#include <cstdint>

// Causal GQA flash attention, TF32 mma.sync, fp32 I/O.
// Shapes hardcoded: B=4, S=2048, H=16, KH=4, D=128.
// BQ=128 (8 warps x 16 rows), BK=64. 1 CTA/SM.
// R16: R10 compute structure (NO Q-register hoist -- every kernel with the
//      hoist hit 255 regs + spills and regressed; R10 without it: 192 regs,
//      590us) + cp.async pipelining: K double-buffered (hidden under full
//      tile), V single-buffered (hidden under S-compute+softmax).
//      K/V enter smem as raw fp32; mma.tf32 truncates in HW (rel_err 7.7e-4
//      measured in R15, deterministic seed).

namespace {
constexpr int B_ = 4, S_ = 2048, H_ = 16, KH_ = 4, D_ = 128;
constexpr int BQ = 128, BK = 64;
constexpr int NTQ = S_ / BQ;            // 16 q-tiles per (b,h)
constexpr int QSTR = 132;               // bank (4g+tg) conflict-free
constexpr int KSTR = 132;
constexpr int VSTR = 136;               // bank (8tg+g) conflict-free
constexpr int PSTR = 68;                // bank (4g+tg) conflict-free
constexpr int NWARP = 8, THREADS = 256;
constexpr float SCALE_LOG2E = 0.08838834764831845f * 1.4426950408889634f;
// smem layout (floats): Q | K0 | K1 | V | P  = 204.8 KB
constexpr int OFF_Q  = 0;
constexpr int OFF_K0 = OFF_Q + BQ * QSTR;             // 16896
constexpr int OFF_K1 = OFF_K0 + BK * KSTR;            // 25344
constexpr int OFF_V  = OFF_K1 + BK * KSTR;            // 33792
constexpr int OFF_P  = OFF_V + BK * VSTR;             // 42496
constexpr int SMEM_FLOATS = OFF_P + NWARP * 16 * PSTR;  // 51200
constexpr size_t SMEM_BYTES = SMEM_FLOATS * sizeof(float);  // 204,800 B
}  // namespace

__device__ __forceinline__ uint32_t f2tf(float x) {
  uint32_t r;
  asm("cvt.rna.tf32.f32 %0, %1;" : "=r"(r) : "f"(x));
  return r;
}

__device__ __forceinline__ void mma8(float c[4], uint32_t a0, uint32_t a1,
                                     uint32_t a2, uint32_t a3, uint32_t b0,
                                     uint32_t b1) {
  asm volatile(
      "mma.sync.aligned.m16n8k8.row.col.f32.tf32.tf32.f32 "
      "{%0,%1,%2,%3}, {%4,%5,%6,%7}, {%8,%9}, {%0,%1,%2,%3};"
      : "+f"(c[0]), "+f"(c[1]), "+f"(c[2]), "+f"(c[3])
      : "r"(a0), "r"(a1), "r"(a2), "r"(a3), "r"(b0), "r"(b1));
}

__device__ __forceinline__ void cpa16(uint32_t smem_addr, const void* gptr) {
  asm volatile("cp.async.cg.shared.global [%0], [%1], 16;" ::"r"(smem_addr),
               "l"(gptr));
}

// One tensor tile (64 rows x 128 fp32): 2048 16B chunks, 8 per thread.
__device__ __forceinline__ void issue_tile(const float* __restrict__ gb,
                                           uint32_t sa, int stride_f,
                                           int tid) {
#pragma unroll
  for (int it = 0; it < 8; ++it) {
    int i = tid + it * THREADS;
    int row = i >> 5;            // 0..63
    int c4 = (i & 31) << 2;      // 0..124 floats, 16B-aligned
    cpa16(sa + (row * stride_f + c4) * 4, gb + (size_t)row * KH_ * D_ + c4);
  }
  asm volatile("cp.async.commit_group;");
}

__global__ __launch_bounds__(THREADS, 1)
void fa_tf32_kernel(const float* __restrict__ q, const float* __restrict__ k,
                    const float* __restrict__ v, float* __restrict__ out) {
  extern __shared__ float sm[];
  uint32_t* smu = (uint32_t*)sm;
  uint32_t* sQ = smu + OFF_Q;
  uint32_t* sKb[2] = {smu + OFF_K0, smu + OFF_K1};
  uint32_t* sV = smu + OFF_V;
  uint32_t* sP = smu + OFF_P;
  const uint32_t smem_base = (uint32_t)__cvta_generic_to_shared(sm);
  const uint32_t aK[2] = {smem_base + OFF_K0 * 4, smem_base + OFF_K1 * 4};
  const uint32_t aV = smem_base + OFF_V * 4;

  const int bx = blockIdx.x;
  const int iq = NTQ - 1 - bx / (B_ * H_);   // longest CTAs first
  const int bh = bx % (B_ * H_);
  const int b = bh / H_, h = bh % H_;
  const int kvh = h / (H_ / KH_);            // GQA: jnp.repeat -> h // 4
  const int q0 = iq * BQ;

  const int tid = threadIdx.x;
  const int w = tid >> 5, lane = tid & 31;
  const int g = lane >> 2, tg = lane & 3;
  const int r0 = w * 16;
  uint32_t* sPw = sP + w * 16 * PSTR;

  const int jmax = 2 * iq + 1;
  const float* kh_base = k + ((size_t)b * S_ * KH_ + kvh) * D_;
  const float* vh_base = v + ((size_t)b * S_ * KH_ + kvh) * D_;

  // preload K tile 0 (group pending), then stage Q while it flies
  issue_tile(kh_base, aK[0], KSTR, tid);

  // ---- stage Q tile (128 x 128), fp32 -> tf32 RNA (loaded once) ----
  const float* qbase = q + ((size_t)(b * S_ + q0) * H_ + h) * D_;
  for (int i = tid; i < BQ * (D_ / 4); i += THREADS) {
    int row = i >> 5, c4 = (i & 31) << 2;
    float4 x = *(const float4*)(qbase + (size_t)row * H_ * D_ + c4);
    uint4 t = {f2tf(x.x), f2tf(x.y), f2tf(x.z), f2tf(x.w)};
    *(uint4*)(sQ + row * QSTR + c4) = t;
  }

  float o[16][4];
#pragma unroll
  for (int i = 0; i < 16; i++) {
    o[i][0] = 0.f; o[i][1] = 0.f; o[i][2] = 0.f; o[i][3] = 0.f;
  }
  float mA = -1e30f, mB = -1e30f, lA = 0.f, lB = 0.f;

  for (int j = 0; j <= jmax; ++j) {
    const int kbase = j * BK;
    // issue V(j) (single buffer; WAR covered by end-of-tile barrier), then
    // K(j+1) into the other K buffer (WAR covered by mid-tile barrier).
    issue_tile(vh_base + (size_t)kbase * KH_ * D_, aV, VSTR, tid);
    if (j < jmax) {
      issue_tile(kh_base + (size_t)(j + 1) * BK * KH_ * D_, aK[(j + 1) & 1],
                 KSTR, tid);
      asm volatile("cp.async.wait_group 2;");  // K(j) arrived
    } else {
      asm volatile("cp.async.wait_group 1;");  // K(j) arrived
    }
    __syncthreads();  // K(j) + Q (j==0) visible to all warps

    const uint32_t* sK = sKb[j & 1];
    // warp-uniform skip of fully-masked tiles; every surviving row has >= 1
    // unmasked key (kbase % 64 == 0, (q0+r0) % 16 == 0)
    const bool active = (kbase <= q0 + r0);

    float sacc[8][4];
    if (active) {
      // ---- S = Q K^T (16x64 per warp; 8 n-tiles, 16 k-steps over D) ----
      // K holds raw fp32 bits; mma.tf32 truncates (RZ) in hardware.
#pragma unroll
      for (int nt = 0; nt < 8; nt++) {
        sacc[nt][0] = 0.f; sacc[nt][1] = 0.f;
        sacc[nt][2] = 0.f; sacc[nt][3] = 0.f;
      }
#pragma unroll
      for (int kk = 0; kk < 16; ++kk) {
        const int col = kk * 8 + tg;
        uint32_t a0 = sQ[(r0 + g) * QSTR + col];
        uint32_t a1 = sQ[(r0 + g + 8) * QSTR + col];
        uint32_t a2 = sQ[(r0 + g) * QSTR + col + 4];
        uint32_t a3 = sQ[(r0 + g + 8) * QSTR + col + 4];
#pragma unroll
        for (int nt = 0; nt < 8; ++nt) {
          uint32_t b0 = sK[(nt * 8 + g) * KSTR + col];
          uint32_t b1 = sK[(nt * 8 + g) * KSTR + col + 4];
          mma8(sacc[nt], a0, a1, a2, a3, b0, b1);
        }
      }

      // ---- scale + causal mask (log2 domain) ----
      const bool needMask = (kbase + BK - 1) > (q0 + r0);
#pragma unroll
      for (int nt = 0; nt < 8; ++nt) {
#pragma unroll
        for (int sl = 0; sl < 4; ++sl) {
          float t = sacc[nt][sl] * SCALE_LOG2E;
          if (needMask) {
            int qrow = q0 + r0 + g + ((sl & 2) ? 8 : 0);
            int kcol = kbase + nt * 8 + 2 * tg + (sl & 1);
            if (kcol > qrow) t = -1e30f;
          }
          sacc[nt][sl] = t;
        }
      }

      // ---- online softmax (rows g -> A, rows g+8 -> B) ----
      float txA = -1e30f, txB = -1e30f;
#pragma unroll
      for (int nt = 0; nt < 8; ++nt) {
        txA = fmaxf(txA, fmaxf(sacc[nt][0], sacc[nt][1]));
        txB = fmaxf(txB, fmaxf(sacc[nt][2], sacc[nt][3]));
      }
      txA = fmaxf(txA, __shfl_xor_sync(0xffffffffu, txA, 1));
      txA = fmaxf(txA, __shfl_xor_sync(0xffffffffu, txA, 2));
      txB = fmaxf(txB, __shfl_xor_sync(0xffffffffu, txB, 1));
      txB = fmaxf(txB, __shfl_xor_sync(0xffffffffu, txB, 2));
      const float mnA = fmaxf(mA, txA), mnB = fmaxf(mB, txB);
      const float alA = exp2f(mA - mnA), alB = exp2f(mB - mnB);
      mA = mnA; mB = mnB;
      float rsA = 0.f, rsB = 0.f;
#pragma unroll
      for (int nt = 0; nt < 8; ++nt) {
        float p0 = exp2f(sacc[nt][0] - mnA);
        float p1 = exp2f(sacc[nt][1] - mnA);
        float p2 = exp2f(sacc[nt][2] - mnB);
        float p3 = exp2f(sacc[nt][3] - mnB);
        rsA += p0 + p1; rsB += p2 + p3;
        sacc[nt][0] = p0; sacc[nt][1] = p1;
        sacc[nt][2] = p2; sacc[nt][3] = p3;
      }
      rsA += __shfl_xor_sync(0xffffffffu, rsA, 1);
      rsA += __shfl_xor_sync(0xffffffffu, rsA, 2);
      rsB += __shfl_xor_sync(0xffffffffu, rsB, 1);
      rsB += __shfl_xor_sync(0xffffffffu, rsB, 2);
      lA = lA * alA + rsA;
      lB = lB * alB + rsB;
#pragma unroll
      for (int nt = 0; nt < 16; ++nt) {
        o[nt][0] *= alA; o[nt][1] *= alA; o[nt][2] *= alB; o[nt][3] *= alB;
      }

      // ---- P -> per-warp smem (C-layout -> A-layout remap), RNA cvt ----
#pragma unroll
      for (int nt = 0; nt < 8; ++nt) {
        uint2 pA = {f2tf(sacc[nt][0]), f2tf(sacc[nt][1])};
        *(uint2*)(sPw + g * PSTR + nt * 8 + 2 * tg) = pA;
        uint2 pB = {f2tf(sacc[nt][2]), f2tf(sacc[nt][3])};
        *(uint2*)(sPw + (g + 8) * PSTR + nt * 8 + 2 * tg) = pB;
      }
      __syncwarp();
    }  // active (part 1)

    // V(j) arrival: its group is the last-but-(j<jmax) committed
    if (j < jmax) {
      asm volatile("cp.async.wait_group 1;");  // V(j) done, K(j+1) pending
    } else {
      asm volatile("cp.async.wait_group 0;");  // V(j) done
    }
    __syncthreads();  // V(j) visible to all warps; also K-buf WAR for j+1

    if (active) {
      // ---- O += P V (16 n-tiles over D=128, 8 k-steps over keys) ----
      // V raw fp32 bits; mma.tf32 truncates in hardware.
#pragma unroll
      for (int kk = 0; kk < 8; ++kk) {
        const int col = kk * 8 + tg;
        uint32_t a0 = sPw[g * PSTR + col];
        uint32_t a1 = sPw[(g + 8) * PSTR + col];
        uint32_t a2 = sPw[g * PSTR + col + 4];
        uint32_t a3 = sPw[(g + 8) * PSTR + col + 4];
#pragma unroll
        for (int nt = 0; nt < 16; ++nt) {
          uint32_t b0 = sV[(col)*VSTR + nt * 8 + g];
          uint32_t b1 = sV[(col + 4) * VSTR + nt * 8 + g];
          mma8(o[nt], a0, a1, a2, a3, b0, b1);
        }
      }
    }  // active (part 2)
    __syncthreads();  // V-buffer WAR: next iter's cp.async must not overwrite
  }

  // ---- epilogue: O / l, store fp32 ----
  const float ilA = 1.0f / lA;
  const float ilB = 1.0f / lB;
  float* obase = out + ((size_t)(b * S_ + q0 + r0) * H_ + h) * D_;
#pragma unroll
  for (int nt = 0; nt < 16; ++nt) {
    int c = nt * 8 + 2 * tg;
    float2 vA = {o[nt][0] * ilA, o[nt][1] * ilA};
    *(float2*)(obase + (size_t)g * H_ * D_ + c) = vA;
    float2 vB = {o[nt][2] * ilB, o[nt][3] * ilB};
    *(float2*)(obase + (size_t)(g + 8) * H_ * D_ + c) = vB;
  }
}

extern "C" void kernel_launch(void* const* d_in, const int* in_sizes, int n_in,
                              void* d_out, int out_size) {
  const float* q = (const float*)d_in[0];
  const float* k = (const float*)d_in[1];
  const float* v = (const float*)d_in[2];
  // d_in[3] = cu_seqlens: equal-length (arange(B+1)*S), structure hardcoded.
  float* out = (float*)d_out;

  cudaFuncSetAttribute(fa_tf32_kernel,
                       cudaFuncAttributeMaxDynamicSharedMemorySize,
                       (int)SMEM_BYTES);
  dim3 grid(B_ * H_ * NTQ);  // 1024 CTAs, longest (iq=15) first
  fa_tf32_kernel<<<grid, THREADS, SMEM_BYTES>>>(q, k, v, out);
}